// round 14
// baseline (speedup 1.0000x reference)
#include <cuda_runtime.h>
#include <cuda_bf16.h>
#include <cuda_fp16.h>
#include <cstdint>

// ---------------------------------------------------------------------------
// Problem constants
// ---------------------------------------------------------------------------
#define BATCH 2
#define SEQ   2048
#define INF   1024
#define HEADS 8
#define DPH   64
#define OUTF  1024
#define NP    512                 // HEADS*DPH
#define MROWS (BATCH*SEQ)         // 4096
#define PSZ   (MROWS*NP)          // elems per projection
#define CTXROWS (BATCH*HEADS*SEQ) // 32768

// Scratch (module-static device memory; no runtime allocation)
__device__ __half g_Ahi[MROWS * INF];      // inputs fp16 hi (also V-proj A)
__device__ __half g_Alo[MROWS * INF];      // inputs fp16 lo
__device__ __half g_Wthi[2 * NP * INF];    // Wq,Wk ^T fp16 hi [n][k]
__device__ __half g_Wtlo[2 * NP * INF];    // Wq,Wk ^T fp16 lo
__device__ __half g_Wvf[NP * INF];         // Wv^T fp16 single
__device__ __half g_Wof[OUTF * DPH];       // Wo^T fp16 single
__device__ __half g_Qh[PSZ];               // Q fp16 hi
__device__ __half g_Ql[PSZ];               // Q fp16 lo
__device__ __half g_Kf[PSZ];               // K fp16 single
__device__ __half g_Vf[PSZ];               // V fp16 single

// ---------------------------------------------------------------------------
// Helpers
// ---------------------------------------------------------------------------
__device__ __forceinline__ uint32_t smem_u32(const void* p) {
    uint32_t a;
    asm("{ .reg .u64 t; cvta.to.shared.u64 t, %1; cvt.u32.u64 %0, t; }"
        : "=r"(a) : "l"(p));
    return a;
}

// fp16 inputs, fp32 accumulate
__device__ __forceinline__ void mma16816h(float d[4], const uint32_t a[4],
                                          const uint32_t b[2], const float c[4]) {
    asm volatile(
        "mma.sync.aligned.m16n8k16.row.col.f32.f16.f16.f32 "
        "{%0,%1,%2,%3}, {%4,%5,%6,%7}, {%8,%9}, {%10,%11,%12,%13};"
        : "=f"(d[0]), "=f"(d[1]), "=f"(d[2]), "=f"(d[3])
        : "r"(a[0]), "r"(a[1]), "r"(a[2]), "r"(a[3]),
          "r"(b[0]), "r"(b[1]),
          "f"(c[0]), "f"(c[1]), "f"(c[2]), "f"(c[3]));
}

__device__ __forceinline__ void ldsm4(uint32_t r[4], uint32_t addr) {
    asm volatile("ldmatrix.sync.aligned.m8n8.x4.shared.b16 {%0,%1,%2,%3}, [%4];"
                 : "=r"(r[0]), "=r"(r[1]), "=r"(r[2]), "=r"(r[3]) : "r"(addr));
}
__device__ __forceinline__ void ldsm4t(uint32_t r[4], uint32_t addr) {
    asm volatile("ldmatrix.sync.aligned.m8n8.x4.trans.shared.b16 {%0,%1,%2,%3}, [%4];"
                 : "=r"(r[0]), "=r"(r[1]), "=r"(r[2]), "=r"(r[3]) : "r"(addr));
}

#define CP_A16(dst, src) \
    asm volatile("cp.async.cg.shared.global [%0], [%1], 16;" :: "r"(dst), "l"(src) : "memory")
#define CP_COMMIT() asm volatile("cp.async.commit_group;" ::: "memory")
#define CP_WAIT0()  asm volatile("cp.async.wait_group 0;" ::: "memory")
#define CP_WAIT1()  asm volatile("cp.async.wait_group 1;" ::: "memory")
#define CP_WAIT2()  asm volatile("cp.async.wait_group 2;" ::: "memory")

__device__ __forceinline__ void splith(float v, __half& h, __half& l) {
    h = __float2half_rn(v);
    l = __float2half_rn(v - __half2float(h));
}
__device__ __forceinline__ uint32_t pack2h(__half a, __half b) {
    __half2 p = __halves2half2(a, b);
    return *reinterpret_cast<uint32_t*>(&p);
}
__device__ __forceinline__ uint32_t packh2(float a, float b) {
    __half2 p = __floats2half2_rn(a, b);
    return *reinterpret_cast<uint32_t*>(&p);
}

// strides (elements) for mma operand tiles in smem
#define STR  72   // 144 B rows (64-col tiles)
#define STR2 40   // 80 B rows (32-col tiles)

__device__ __forceinline__ uint32_t addrA_s(uint32_t base, int brow, int bcol, int lane, int str) {
    int row = brow + (lane & 7) + ((lane & 8) ? 8 : 0);
    int col = bcol + ((lane & 16) ? 8 : 0);
    return base + (row * str + col) * 2;
}
__device__ __forceinline__ uint32_t addrB_s(uint32_t base, int brow, int bcol, int lane, int str) {
    int row = brow + (lane & 7) + ((lane & 16) ? 8 : 0);
    int col = bcol + ((lane & 8) ? 8 : 0);
    return base + (row * str + col) * 2;
}
__device__ __forceinline__ uint32_t addrV_s(uint32_t base, int kvrow, int dcol, int lane, int str) {
    int row = kvrow + (lane & 7) + ((lane & 8) ? 8 : 0);
    int col = dcol + ((lane & 16) ? 8 : 0);
    return base + (row * str + col) * 2;
}

// ---------------------------------------------------------------------------
// Fused prep kernel: one launch, block-range dispatch into three paths.
// ---------------------------------------------------------------------------
#define PREP_A_BLKS  (MROWS * INF / 4 / 256)   // 4096
#define PREP_WT_BLKS (3 * (INF/32) * (NP/32))  // 1536
#define PREP_WO_BLKS ((DPH/32) * (OUTF/32))    // 64

__global__ __launch_bounds__(256) void prep_all(const float* __restrict__ X,
                                                const float* __restrict__ Wq,
                                                const float* __restrict__ Wk,
                                                const float* __restrict__ Wv,
                                                const float* __restrict__ Wo) {
    __shared__ float t[32][33];
    const int blk = blockIdx.x;
    const int tid = threadIdx.x;

    if (blk < PREP_A_BLKS) {
        int idx = blk * 256 + tid;
        float4 v = ((const float4*)X)[idx];
        __half h0, h1, h2, h3, l0, l1, l2, l3;
        splith(v.x, h0, l0); splith(v.y, h1, l1);
        splith(v.z, h2, l2); splith(v.w, h3, l3);
        uint2 hh; hh.x = pack2h(h0, h1); hh.y = pack2h(h2, h3);
        uint2 ll; ll.x = pack2h(l0, l1); ll.y = pack2h(l2, l3);
        ((uint2*)g_Ahi)[idx] = hh;
        ((uint2*)g_Alo)[idx] = ll;
    } else if (blk < PREP_A_BLKS + PREP_WT_BLKS) {
        int i = blk - PREP_A_BLKS;
        const int which = i / 512;
        int j = i % 512;
        const int k0 = (j % 32) * 32, n0 = (j / 32) * 32;
        const float* W = (which == 0) ? Wq : (which == 1) ? Wk : Wv;
        const int tx = tid & 31, ty = tid >> 5;
#pragma unroll
        for (int jj = 0; jj < 4; jj++)
            t[ty + jj * 8][tx] = W[(size_t)(k0 + ty + jj * 8) * NP + n0 + tx];
        __syncthreads();
#pragma unroll
        for (int jj = 0; jj < 4; jj++) {
            int n = n0 + ty + jj * 8, k = k0 + tx;
            float v = t[tx][ty + jj * 8];
            if (which < 2) {
                __half h, l; splith(v, h, l);
                size_t o = ((size_t)which * NP + n) * INF + k;
                g_Wthi[o] = h; g_Wtlo[o] = l;
            } else {
                g_Wvf[(size_t)n * INF + k] = __float2half_rn(v);
            }
        }
    } else {
        int i = blk - PREP_A_BLKS - PREP_WT_BLKS;
        const int k0 = (i % 2) * 32, n0 = (i / 2) * 32;
        const int tx = tid & 31, ty = tid >> 5;
#pragma unroll
        for (int jj = 0; jj < 4; jj++)
            t[ty + jj * 8][tx] = Wo[(size_t)(k0 + ty + jj * 8) * OUTF + n0 + tx];
        __syncthreads();
#pragma unroll
        for (int jj = 0; jj < 4; jj++) {
            int n = n0 + ty + jj * 8, k = k0 + tx;
            g_Wof[(size_t)n * DPH + k] = __float2half_rn(t[tx][ty + jj * 8]);
        }
    }
}

// ---------------------------------------------------------------------------
// Kernel 1: fused QKV. Top-level dispatch on blockIdx.z into two SEPARATE
// fully-pipelined paths.
// ---------------------------------------------------------------------------
#define Q2_MAT (128*STR2*2)        // 10240 per matrix
#define Q2_AH 0
#define Q2_AL Q2_MAT
#define Q2_BH (2*Q2_MAT)
#define Q2_BL (3*Q2_MAT)
#define Q2ST  (4*Q2_MAT)           // 40960 stage stride
#define QG_SMEM (2*Q2ST)           // 81920

#define V_A 0
#define V_B 18432
#define VST 36864                  // V stage stride

__device__ __forceinline__ void qk_path(char* sm, uint32_t sb, int which,
                                        int m0, int n0, int tid, int wid, int lane,
                                        int wm, int wn) {
    const __half* Bh = g_Wthi + (size_t)which * NP * INF;
    const __half* Bl = g_Wtlo + (size_t)which * NP * INF;

    float acc[4][4][4];
#pragma unroll
    for (int mi = 0; mi < 4; mi++)
#pragma unroll
        for (int nj = 0; nj < 4; nj++)
#pragma unroll
            for (int e = 0; e < 4; e++) acc[mi][nj][e] = 0.f;

    auto load_chunk = [&](int c, int stage) {
        uint32_t base = sb + stage * Q2ST;
        const int k0 = c * 32;
#pragma unroll
        for (int i = 0; i < 2; i++) {
            int idx = i * 256 + tid;
            int row = idx >> 2, v = idx & 3;
            uint32_t so = (uint32_t)(row * STR2 + v * 8) * 2;
            size_t gA = (size_t)(m0 + row) * INF + k0 + v * 8;
            size_t gB = (size_t)(n0 + row) * INF + k0 + v * 8;
            CP_A16(base + Q2_AH + so, g_Ahi + gA);
            CP_A16(base + Q2_AL + so, g_Alo + gA);
            CP_A16(base + Q2_BH + so, Bh + gB);
            CP_A16(base + Q2_BL + so, Bl + gB);
        }
        CP_COMMIT();
    };

    load_chunk(0, 0);

    for (int c = 0; c < 32; ++c) {
        const int s = c & 1;
        CP_WAIT0();
        __syncthreads();
        if (c < 31) load_chunk(c + 1, s ^ 1);

        uint32_t base = sb + s * Q2ST;
#pragma unroll
        for (int ki = 0; ki < 2; ki++) {
            uint32_t bh[2][4], bl[2][4];
#pragma unroll
            for (int p = 0; p < 2; p++) {
                ldsm4(bh[p], addrB_s(base + Q2_BH, wn + p * 16, ki * 16, lane, STR2));
                ldsm4(bl[p], addrB_s(base + Q2_BL, wn + p * 16, ki * 16, lane, STR2));
            }
#pragma unroll
            for (int mi = 0; mi < 4; mi++) {
                uint32_t ah[4], al[4];
                ldsm4(ah, addrA_s(base + Q2_AH, wm + mi * 16, ki * 16, lane, STR2));
                ldsm4(al, addrA_s(base + Q2_AL, wm + mi * 16, ki * 16, lane, STR2));
#pragma unroll
                for (int nj = 0; nj < 4; nj++) {
                    const uint32_t* bhp = &bh[nj >> 1][(nj & 1) * 2];
                    const uint32_t* blp = &bl[nj >> 1][(nj & 1) * 2];
                    mma16816h(acc[mi][nj], ah, bhp, acc[mi][nj]);
                    mma16816h(acc[mi][nj], al, bhp, acc[mi][nj]);
                    mma16816h(acc[mi][nj], ah, blp, acc[mi][nj]);
                }
            }
        }
    }

    if (which == 0) {
#pragma unroll
        for (int mi = 0; mi < 4; mi++) {
#pragma unroll
            for (int nj = 0; nj < 4; nj++) {
                int row = m0 + wm + mi * 16 + (lane >> 2);
                int col = n0 + wn + nj * 8 + 2 * (lane & 3);
                __half h0, l0, h1, l1;
                splith(acc[mi][nj][0], h0, l0); splith(acc[mi][nj][1], h1, l1);
                *(uint32_t*)&g_Qh[(size_t)row * NP + col] = pack2h(h0, h1);
                *(uint32_t*)&g_Ql[(size_t)row * NP + col] = pack2h(l0, l1);
                splith(acc[mi][nj][2], h0, l0); splith(acc[mi][nj][3], h1, l1);
                *(uint32_t*)&g_Qh[(size_t)(row + 8) * NP + col] = pack2h(h0, h1);
                *(uint32_t*)&g_Ql[(size_t)(row + 8) * NP + col] = pack2h(l0, l1);
            }
        }
    } else {
#pragma unroll
        for (int mi = 0; mi < 4; mi++) {
#pragma unroll
            for (int nj = 0; nj < 4; nj++) {
                int row = m0 + wm + mi * 16 + (lane >> 2);
                int col = n0 + wn + nj * 8 + 2 * (lane & 3);
                *(uint32_t*)&g_Kf[(size_t)row * NP + col]       = packh2(acc[mi][nj][0], acc[mi][nj][1]);
                *(uint32_t*)&g_Kf[(size_t)(row + 8) * NP + col] = packh2(acc[mi][nj][2], acc[mi][nj][3]);
            }
        }
    }
}

__device__ __forceinline__ void v_path(char* sm, uint32_t sb,
                                       int m0, int n0, int tid, int wid, int lane,
                                       int wm, int wn) {
    float acc[4][4][4];
#pragma unroll
    for (int mi = 0; mi < 4; mi++)
#pragma unroll
        for (int nj = 0; nj < 4; nj++)
#pragma unroll
            for (int e = 0; e < 4; e++) acc[mi][nj][e] = 0.f;

    auto load_chunk = [&](int c, int stage) {
        uint32_t base = sb + stage * VST;
        const int k0 = c * 64;
#pragma unroll
        for (int i = 0; i < 4; i++) {
            int idx = i * 256 + tid;
            int row = idx >> 3, v = idx & 7;
            uint32_t so = (uint32_t)(row * STR + v * 8) * 2;
            CP_A16(base + V_A + so, g_Ahi + (size_t)(m0 + row) * INF + k0 + v * 8);
            CP_A16(base + V_B + so, g_Wvf + (size_t)(n0 + row) * INF + k0 + v * 8);
        }
        CP_COMMIT();
    };

    load_chunk(0, 0);

    for (int c = 0; c < 16; ++c) {
        const int s = c & 1;
        CP_WAIT0();
        __syncthreads();
        if (c < 15) load_chunk(c + 1, s ^ 1);

        uint32_t base = sb + s * VST;
#pragma unroll
        for (int ki = 0; ki < 4; ki++) {
            uint32_t bq[2][4];
#pragma unroll
            for (int p = 0; p < 2; p++)
                ldsm4(bq[p], addrB_s(base + V_B, wn + p * 16, ki * 16, lane, STR));
#pragma unroll
            for (int mi = 0; mi < 4; mi++) {
                uint32_t aq[4];
                ldsm4(aq, addrA_s(base + V_A, wm + mi * 16, ki * 16, lane, STR));
#pragma unroll
                for (int nj = 0; nj < 4; nj++)
                    mma16816h(acc[mi][nj], aq, &bq[nj >> 1][(nj & 1) * 2], acc[mi][nj]);
            }
        }
    }

#pragma unroll
    for (int mi = 0; mi < 4; mi++) {
#pragma unroll
        for (int nj = 0; nj < 4; nj++) {
            int row = m0 + wm + mi * 16 + (lane >> 2);
            int col = n0 + wn + nj * 8 + 2 * (lane & 3);
            *(uint32_t*)&g_Vf[(size_t)row * NP + col]       = packh2(acc[mi][nj][0], acc[mi][nj][1]);
            *(uint32_t*)&g_Vf[(size_t)(row + 8) * NP + col] = packh2(acc[mi][nj][2], acc[mi][nj][3]);
        }
    }
}

__global__ __launch_bounds__(256, 2) void qkv_mma() {
    extern __shared__ char sm[];
    uint32_t sb = smem_u32(sm);
    const int which = blockIdx.z;            // 0=Q, 1=K, 2=V
    const int m0 = blockIdx.y * 128;
    const int n0 = blockIdx.x * 128;
    const int tid = threadIdx.x, wid = tid >> 5, lane = tid & 31;
    const int wm = (wid >> 2) * 64;
    const int wn = (wid & 3) * 32;

    if (which < 2)
        qk_path(sm, sb, which, m0, n0, tid, wid, lane, wm, wn);
    else
        v_path(sm, sb, m0, n0, tid, wid, lane, wm, wn);
}

// ---------------------------------------------------------------------------
// Kernel 2: FA2 flash attention + FUSED output projection.
// 128 q-rows, 256 threads, KV chunks 64, 3-stage cp.async pipeline.
// QK: 2 fp16 MMAs. PV: 1 MMA. Epilogue: ctx (regs, fp16) @ Wo + bo -> out,
// N chunks of 64, Wo staged via 4-deep cp.async pipeline in KV smem region.
// ---------------------------------------------------------------------------
#define AQ_H 0
#define AQ_L 18432
#define A_KV0 36864
#define A_KF 0
#define A_VF 9216
#define AST  18432                  // stage stride (K fp16 + V fp16)
#define AT_SMEM (A_KV0 + 3*AST)     // 92160
#define WO_ST 9216                  // Wo chunk stage stride (64 rows x STR)

__global__ __launch_bounds__(256, 2) void attn_fa2(const float* __restrict__ bo,
                                                   float* __restrict__ out) {
    extern __shared__ char sm[];
    uint32_t sb = smem_u32(sm);
    const int bh = blockIdx.y;
    const int b = bh >> 3, h = bh & 7;
    const size_t hoff = ((size_t)b * SEQ + (size_t)h * 256) * NP;
    const __half* Qh = g_Qh + hoff;
    const __half* Ql = g_Ql + hoff;
    const __half* Kf = g_Kf + hoff;
    const __half* Vf = g_Vf + hoff;

    const int q0 = blockIdx.x * 128;
    const int tid = threadIdx.x, wid = tid >> 5, lane = tid & 31;

    auto load_kv = [&](int kt, int stage) {
        uint32_t base = sb + A_KV0 + stage * AST;
#pragma unroll
        for (int i = 0; i < 2; i++) {
            int id2 = i * 256 + tid;
            int row = id2 >> 3, v = id2 & 7;
            uint32_t so = (uint32_t)(row * STR + v * 8) * 2;
            size_t g = (size_t)(kt * 64 + row) * DPH + v * 8;
            CP_A16(base + A_KF + so, Kf + g);
            CP_A16(base + A_VF + so, Vf + g);
        }
        CP_COMMIT();
    };

    // Persistent Q region (fp16 hi + lo)
#pragma unroll
    for (int i = 0; i < 4; i++) {
        int idx = i * 256 + tid;
        int row = idx >> 3, v = idx & 7;
        uint32_t so = (uint32_t)(row * STR + v * 8) * 2;
        size_t g = (size_t)(q0 + row) * DPH + v * 8;
        *(uint4*)(sm + AQ_H + so) = *(const uint4*)(Qh + g);
        *(uint4*)(sm + AQ_L + so) = *(const uint4*)(Ql + g);
    }
    load_kv(0, 0);
    load_kv(1, 1);
    __syncthreads();

    uint32_t aqh[4][4];
#pragma unroll
    for (int ki = 0; ki < 4; ki++)
        ldsm4(aqh[ki], addrA_s(sb + AQ_H, wid * 16, ki * 16, lane, STR));

    float cacc[8][4];
#pragma unroll
    for (int nj = 0; nj < 8; nj++)
#pragma unroll
        for (int e = 0; e < 4; e++) cacc[nj][e] = 0.f;
    float m0 = -1e30f, m1 = -1e30f, l0 = 0.f, l1 = 0.f;

    int stage = 0;   // stage of chunk kt
    for (int kt = 0; kt < 32; kt++) {
        if (kt < 31) { CP_WAIT1(); } else { CP_WAIT0(); }
        __syncthreads();
        if (kt < 30) {
            int ns = stage + 2; if (ns >= 3) ns -= 3;
            load_kv(kt + 2, ns);
        }

        uint32_t base = sb + A_KV0 + stage * AST;

        // S = Q @ K^T (qh*k + ql*k, both fp32 acc)
        float sacc[8][4];
#pragma unroll
        for (int nj = 0; nj < 8; nj++)
#pragma unroll
            for (int e = 0; e < 4; e++) sacc[nj][e] = 0.f;
#pragma unroll
        for (int ki = 0; ki < 4; ki++) {
            uint32_t aql[4];
            ldsm4(aql, addrA_s(sb + AQ_L, wid * 16, ki * 16, lane, STR));
#pragma unroll
            for (int p = 0; p < 4; p++) {
                uint32_t kf2[4];
                ldsm4(kf2, addrB_s(base + A_KF, p * 16, ki * 16, lane, STR));
#pragma unroll
                for (int q = 0; q < 2; q++) {
                    int nj = 2 * p + q;
                    mma16816h(sacc[nj], aqh[ki], &kf2[q * 2], sacc[nj]);
                    mma16816h(sacc[nj], aql,     &kf2[q * 2], sacc[nj]);
                }
            }
        }

        // register softmax: rows r=lane>>2 (m0/l0) and r+8 (m1/l1)
        float mx0 = -1e30f, mx1 = -1e30f;
#pragma unroll
        for (int nj = 0; nj < 8; nj++) {
            mx0 = fmaxf(mx0, fmaxf(sacc[nj][0], sacc[nj][1]));
            mx1 = fmaxf(mx1, fmaxf(sacc[nj][2], sacc[nj][3]));
        }
        mx0 = fmaxf(mx0, __shfl_xor_sync(0xffffffffu, mx0, 1));
        mx0 = fmaxf(mx0, __shfl_xor_sync(0xffffffffu, mx0, 2));
        mx1 = fmaxf(mx1, __shfl_xor_sync(0xffffffffu, mx1, 1));
        mx1 = fmaxf(mx1, __shfl_xor_sync(0xffffffffu, mx1, 2));
        float mn0 = fmaxf(m0, mx0), mn1 = fmaxf(m1, mx1);
        float c0 = __expf(m0 - mn0), c1 = __expf(m1 - mn1);
        m0 = mn0; m1 = mn1;

        uint32_t aP[4][4];
        float ls0 = 0.f, ls1 = 0.f;
#pragma unroll
        for (int ki = 0; ki < 4; ki++) {
#pragma unroll
            for (int jj = 0; jj < 2; jj++) {
                int nj = 2 * ki + jj;
                float p0 = __expf(sacc[nj][0] - mn0);
                float p1 = __expf(sacc[nj][1] - mn0);
                float p2 = __expf(sacc[nj][2] - mn1);
                float p3 = __expf(sacc[nj][3] - mn1);
                ls0 += p0 + p1; ls1 += p2 + p3;
                aP[ki][2 * jj + 0] = packh2(p0, p1);
                aP[ki][2 * jj + 1] = packh2(p2, p3);
            }
        }
        ls0 += __shfl_xor_sync(0xffffffffu, ls0, 1);
        ls0 += __shfl_xor_sync(0xffffffffu, ls0, 2);
        ls1 += __shfl_xor_sync(0xffffffffu, ls1, 1);
        ls1 += __shfl_xor_sync(0xffffffffu, ls1, 2);
        l0 = l0 * c0 + ls0;
        l1 = l1 * c1 + ls1;

#pragma unroll
        for (int nj = 0; nj < 8; nj++) {
            cacc[nj][0] *= c0; cacc[nj][1] *= c0;
            cacc[nj][2] *= c1; cacc[nj][3] *= c1;
        }

        // PV: single fp16 MMA per tile (fp32 acc)
#pragma unroll
        for (int ki = 0; ki < 4; ki++) {
#pragma unroll
            for (int p = 0; p < 4; p++) {
                uint32_t v2[4];
                ldsm4t(v2, addrV_s(base + A_VF, ki * 16, p * 16, lane, STR));
#pragma unroll
                for (int q = 0; q < 2; q++) {
                    int nj = 2 * p + q;
                    mma16816h(cacc[nj], aP[ki], &v2[q * 2], cacc[nj]);
                }
            }
        }

        if (++stage == 3) stage = 0;
    }

    // ---- fused output projection ----
    float inv0 = 1.0f / (8.0f * l0);   // post-softmax /sqrt(d) quirk
    float inv1 = 1.0f / (8.0f * l1);

    // ctx -> fp16 A-fragments (same quantization as the former g_Cf store)
    uint32_t aC[4][4];
#pragma unroll
    for (int ki = 0; ki < 4; ki++) {
#pragma unroll
        for (int jj = 0; jj < 2; jj++) {
            int nj = 2 * ki + jj;
            aC[ki][2 * jj + 0] = packh2(cacc[nj][0] * inv0, cacc[nj][1] * inv0);
            aC[ki][2 * jj + 1] = packh2(cacc[nj][2] * inv1, cacc[nj][3] * inv1);
        }
    }
    __syncthreads();   // all warps done reading KV smem stages

    // Wo pipeline: 4 stages x 9216 B in the dead KV region, 3 loads in flight.
    // FULL 64x64 tile: 64 rows x 8 uint4 = 512 v16 loads / 256 threads = 2 each
    const uint32_t WOB = sb + A_KV0;
    auto load_wo = [&](int ch, int st) {
#pragma unroll
        for (int i = 0; i < 2; i++) {
            int idx = i * 256 + tid;
            int wrow = idx >> 3, wv = idx & 7;
            uint32_t so = (uint32_t)(wrow * STR + wv * 8) * 2;
            CP_A16(WOB + st * WO_ST + so,
                   g_Wof + (size_t)(ch * 64 + wrow) * DPH + wv * 8);
        }
        CP_COMMIT();
    };
    load_wo(0, 0);
    load_wo(1, 1);
    load_wo(2, 2);

    const size_t grow = (size_t)bh * SEQ + q0 + wid * 16 + (lane >> 2);
    for (int ch = 0; ch < 16; ch++) {
        const int st = ch & 3;
        CP_WAIT2();            // chunk ch complete: issued ch+3, outstanding <=2
        __syncthreads();       // all warps done with stage (ch-1)&3 before overwrite
        if (ch < 13) load_wo(ch + 3, (ch + 3) & 3);

        uint32_t base = WOB + st * WO_ST;
        float oacc[8][4];
#pragma unroll
        for (int nj = 0; nj < 8; nj++)
#pragma unroll
            for (int e = 0; e < 4; e++) oacc[nj][e] = 0.f;

#pragma unroll
        for (int ki = 0; ki < 4; ki++) {
#pragma unroll
            for (int p = 0; p < 4; p++) {
                uint32_t bq[4];
                ldsm4(bq, addrB_s(base, p * 16, ki * 16, lane, STR));
#pragma unroll
                for (int q = 0; q < 2; q++) {
                    int nj = 2 * p + q;
                    mma16816h(oacc[nj], aC[ki], &bq[q * 2], oacc[nj]);
                }
            }
        }

        const int nc0 = ch * 64;
#pragma unroll
        for (int nj = 0; nj < 8; nj++) {
            int col = nc0 + nj * 8 + 2 * (lane & 3);
            float2 bv = *(const float2*)&bo[col];
            *(float2*)&out[grow * OUTF + col] =
                make_float2(oacc[nj][0] + bv.x, oacc[nj][1] + bv.y);
            *(float2*)&out[(grow + 8) * OUTF + col] =
                make_float2(oacc[nj][2] + bv.x, oacc[nj][3] + bv.y);
        }
    }
}

// ---------------------------------------------------------------------------
extern "C" void kernel_launch(void* const* d_in, const int* in_sizes, int n_in,
                              void* d_out, int out_size)
{
    const float* inputs = (const float*)d_in[0];
    const float* Wq     = (const float*)d_in[1];
    const float* Wk     = (const float*)d_in[2];
    const float* Wv     = (const float*)d_in[3];
    const float* Wo     = (const float*)d_in[4];
    const float* bo     = (const float*)d_in[5];
    float* out = (float*)d_out;

    cudaFuncSetAttribute(qkv_mma, cudaFuncAttributeMaxDynamicSharedMemorySize, QG_SMEM);
    cudaFuncSetAttribute(attn_fa2, cudaFuncAttributeMaxDynamicSharedMemorySize, AT_SMEM);

    prep_all<<<PREP_A_BLKS + PREP_WT_BLKS + PREP_WO_BLKS, 256>>>(inputs, Wq, Wk, Wv, Wo);
    {
        dim3 grid(NP / 128, MROWS / 128, 3);   // z: Q, K, V — one launch, two code paths
        qkv_mma<<<grid, 256, QG_SMEM>>>();
    }
    {
        dim3 grid(SEQ / 128, BATCH * HEADS);
        attn_fa2<<<grid, 256, AT_SMEM>>>(bo, out);
    }
}

// round 15
// speedup vs baseline: 1.0019x; 1.0019x over previous
#include <cuda_runtime.h>
#include <cuda_bf16.h>
#include <cuda_fp16.h>
#include <cstdint>

// ---------------------------------------------------------------------------
// Problem constants
// ---------------------------------------------------------------------------
#define BATCH 2
#define SEQ   2048
#define INF   1024
#define HEADS 8
#define DPH   64
#define OUTF  1024
#define NP    512                 // HEADS*DPH
#define MROWS (BATCH*SEQ)         // 4096
#define PSZ   (MROWS*NP)          // elems per projection
#define CTXROWS (BATCH*HEADS*SEQ) // 32768
#define LOG2E 1.4426950408889634f

// Scratch (module-static device memory; no runtime allocation)
__device__ __half g_Ahi[MROWS * INF];      // inputs fp16 hi (also V-proj A)
__device__ __half g_Alo[MROWS * INF];      // inputs fp16 lo
__device__ __half g_Wthi[2 * NP * INF];    // Wq,Wk ^T fp16 hi [n][k]
__device__ __half g_Wtlo[2 * NP * INF];    // Wq,Wk ^T fp16 lo
__device__ __half g_Wvf[NP * INF];         // Wv^T fp16 single
__device__ __half g_Wof[OUTF * DPH];       // Wo^T fp16 single
__device__ __half g_Qh[PSZ];               // Q fp16 hi
__device__ __half g_Ql[PSZ];               // Q fp16 lo
__device__ __half g_Kf[PSZ];               // K * log2e, fp16 single
__device__ __half g_Vf[PSZ];               // V fp16 single

// ---------------------------------------------------------------------------
// Helpers
// ---------------------------------------------------------------------------
__device__ __forceinline__ uint32_t smem_u32(const void* p) {
    uint32_t a;
    asm("{ .reg .u64 t; cvta.to.shared.u64 t, %1; cvt.u32.u64 %0, t; }"
        : "=r"(a) : "l"(p));
    return a;
}

// fp16 inputs, fp32 accumulate
__device__ __forceinline__ void mma16816h(float d[4], const uint32_t a[4],
                                          const uint32_t b[2], const float c[4]) {
    asm volatile(
        "mma.sync.aligned.m16n8k16.row.col.f32.f16.f16.f32 "
        "{%0,%1,%2,%3}, {%4,%5,%6,%7}, {%8,%9}, {%10,%11,%12,%13};"
        : "=f"(d[0]), "=f"(d[1]), "=f"(d[2]), "=f"(d[3])
        : "r"(a[0]), "r"(a[1]), "r"(a[2]), "r"(a[3]),
          "r"(b[0]), "r"(b[1]),
          "f"(c[0]), "f"(c[1]), "f"(c[2]), "f"(c[3]));
}

__device__ __forceinline__ void ldsm4(uint32_t r[4], uint32_t addr) {
    asm volatile("ldmatrix.sync.aligned.m8n8.x4.shared.b16 {%0,%1,%2,%3}, [%4];"
                 : "=r"(r[0]), "=r"(r[1]), "=r"(r[2]), "=r"(r[3]) : "r"(addr));
}
__device__ __forceinline__ void ldsm4t(uint32_t r[4], uint32_t addr) {
    asm volatile("ldmatrix.sync.aligned.m8n8.x4.trans.shared.b16 {%0,%1,%2,%3}, [%4];"
                 : "=r"(r[0]), "=r"(r[1]), "=r"(r[2]), "=r"(r[3]) : "r"(addr));
}

#define CP_A16(dst, src) \
    asm volatile("cp.async.cg.shared.global [%0], [%1], 16;" :: "r"(dst), "l"(src) : "memory")
#define CP_COMMIT() asm volatile("cp.async.commit_group;" ::: "memory")
#define CP_WAIT0()  asm volatile("cp.async.wait_group 0;" ::: "memory")
#define CP_WAIT1()  asm volatile("cp.async.wait_group 1;" ::: "memory")
#define CP_WAIT2()  asm volatile("cp.async.wait_group 2;" ::: "memory")

__device__ __forceinline__ float ex2f(float x) {
    float r;
    asm("ex2.approx.f32 %0, %1;" : "=f"(r) : "f"(x));
    return r;
}

__device__ __forceinline__ void splith(float v, __half& h, __half& l) {
    h = __float2half_rn(v);
    l = __float2half_rn(v - __half2float(h));
}
__device__ __forceinline__ uint32_t pack2h(__half a, __half b) {
    __half2 p = __halves2half2(a, b);
    return *reinterpret_cast<uint32_t*>(&p);
}
__device__ __forceinline__ uint32_t packh2(float a, float b) {
    __half2 p = __floats2half2_rn(a, b);
    return *reinterpret_cast<uint32_t*>(&p);
}

// strides (elements) for mma operand tiles in smem
#define STR  72   // 144 B rows (64-col tiles)
#define STR2 40   // 80 B rows (32-col tiles)

__device__ __forceinline__ uint32_t addrA_s(uint32_t base, int brow, int bcol, int lane, int str) {
    int row = brow + (lane & 7) + ((lane & 8) ? 8 : 0);
    int col = bcol + ((lane & 16) ? 8 : 0);
    return base + (row * str + col) * 2;
}
__device__ __forceinline__ uint32_t addrB_s(uint32_t base, int brow, int bcol, int lane, int str) {
    int row = brow + (lane & 7) + ((lane & 16) ? 8 : 0);
    int col = bcol + ((lane & 8) ? 8 : 0);
    return base + (row * str + col) * 2;
}
__device__ __forceinline__ uint32_t addrV_s(uint32_t base, int kvrow, int dcol, int lane, int str) {
    int row = kvrow + (lane & 7) + ((lane & 8) ? 8 : 0);
    int col = dcol + ((lane & 16) ? 8 : 0);
    return base + (row * str + col) * 2;
}

// ---------------------------------------------------------------------------
// Fused prep kernel: one launch, block-range dispatch into three paths.
//   A path: 4 float4 per thread (MLP=4) -> 1024 blocks
// ---------------------------------------------------------------------------
#define PREP_A_BLKS  (MROWS * INF / 4 / 256 / 4)  // 1024
#define PREP_WT_BLKS (3 * (INF/32) * (NP/32))     // 1536
#define PREP_WO_BLKS ((DPH/32) * (OUTF/32))       // 64

__global__ __launch_bounds__(256) void prep_all(const float* __restrict__ X,
                                                const float* __restrict__ Wq,
                                                const float* __restrict__ Wk,
                                                const float* __restrict__ Wv,
                                                const float* __restrict__ Wo) {
    __shared__ float t[32][33];
    const int blk = blockIdx.x;
    const int tid = threadIdx.x;

    if (blk < PREP_A_BLKS) {
#pragma unroll
        for (int j = 0; j < 4; j++) {
            int idx = blk * 1024 + j * 256 + tid;
            float4 v = ((const float4*)X)[idx];
            __half h0, h1, h2, h3, l0, l1, l2, l3;
            splith(v.x, h0, l0); splith(v.y, h1, l1);
            splith(v.z, h2, l2); splith(v.w, h3, l3);
            uint2 hh; hh.x = pack2h(h0, h1); hh.y = pack2h(h2, h3);
            uint2 ll; ll.x = pack2h(l0, l1); ll.y = pack2h(l2, l3);
            ((uint2*)g_Ahi)[idx] = hh;
            ((uint2*)g_Alo)[idx] = ll;
        }
    } else if (blk < PREP_A_BLKS + PREP_WT_BLKS) {
        int i = blk - PREP_A_BLKS;
        const int which = i / 512;
        int j = i % 512;
        const int k0 = (j % 32) * 32, n0 = (j / 32) * 32;
        const float* W = (which == 0) ? Wq : (which == 1) ? Wk : Wv;
        const int tx = tid & 31, ty = tid >> 5;
#pragma unroll
        for (int jj = 0; jj < 4; jj++)
            t[ty + jj * 8][tx] = W[(size_t)(k0 + ty + jj * 8) * NP + n0 + tx];
        __syncthreads();
#pragma unroll
        for (int jj = 0; jj < 4; jj++) {
            int n = n0 + ty + jj * 8, k = k0 + tx;
            float v = t[tx][ty + jj * 8];
            if (which < 2) {
                __half h, l; splith(v, h, l);
                size_t o = ((size_t)which * NP + n) * INF + k;
                g_Wthi[o] = h; g_Wtlo[o] = l;
            } else {
                g_Wvf[(size_t)n * INF + k] = __float2half_rn(v);
            }
        }
    } else {
        int i = blk - PREP_A_BLKS - PREP_WT_BLKS;
        const int k0 = (i % 2) * 32, n0 = (i / 2) * 32;
        const int tx = tid & 31, ty = tid >> 5;
#pragma unroll
        for (int jj = 0; jj < 4; jj++)
            t[ty + jj * 8][tx] = Wo[(size_t)(k0 + ty + jj * 8) * OUTF + n0 + tx];
        __syncthreads();
#pragma unroll
        for (int jj = 0; jj < 4; jj++) {
            int n = n0 + ty + jj * 8, k = k0 + tx;
            g_Wof[(size_t)n * DPH + k] = __float2half_rn(t[tx][ty + jj * 8]);
        }
    }
}

// ---------------------------------------------------------------------------
// Kernel 1: fused QKV. Top-level dispatch on blockIdx.z into two SEPARATE
// fully-pipelined paths. K is stored pre-scaled by log2(e).
// ---------------------------------------------------------------------------
#define Q2_MAT (128*STR2*2)        // 10240 per matrix
#define Q2_AH 0
#define Q2_AL Q2_MAT
#define Q2_BH (2*Q2_MAT)
#define Q2_BL (3*Q2_MAT)
#define Q2ST  (4*Q2_MAT)           // 40960 stage stride
#define QG_SMEM (2*Q2ST)           // 81920

#define V_A 0
#define V_B 18432
#define VST 36864                  // V stage stride

__device__ __forceinline__ void qk_path(char* sm, uint32_t sb, int which,
                                        int m0, int n0, int tid, int wid, int lane,
                                        int wm, int wn) {
    const __half* Bh = g_Wthi + (size_t)which * NP * INF;
    const __half* Bl = g_Wtlo + (size_t)which * NP * INF;

    float acc[4][4][4];
#pragma unroll
    for (int mi = 0; mi < 4; mi++)
#pragma unroll
        for (int nj = 0; nj < 4; nj++)
#pragma unroll
            for (int e = 0; e < 4; e++) acc[mi][nj][e] = 0.f;

    auto load_chunk = [&](int c, int stage) {
        uint32_t base = sb + stage * Q2ST;
        const int k0 = c * 32;
#pragma unroll
        for (int i = 0; i < 2; i++) {
            int idx = i * 256 + tid;
            int row = idx >> 2, v = idx & 3;
            uint32_t so = (uint32_t)(row * STR2 + v * 8) * 2;
            size_t gA = (size_t)(m0 + row) * INF + k0 + v * 8;
            size_t gB = (size_t)(n0 + row) * INF + k0 + v * 8;
            CP_A16(base + Q2_AH + so, g_Ahi + gA);
            CP_A16(base + Q2_AL + so, g_Alo + gA);
            CP_A16(base + Q2_BH + so, Bh + gB);
            CP_A16(base + Q2_BL + so, Bl + gB);
        }
        CP_COMMIT();
    };

    load_chunk(0, 0);

    for (int c = 0; c < 32; ++c) {
        const int s = c & 1;
        CP_WAIT0();
        __syncthreads();
        if (c < 31) load_chunk(c + 1, s ^ 1);

        uint32_t base = sb + s * Q2ST;
#pragma unroll
        for (int ki = 0; ki < 2; ki++) {
            uint32_t bh[2][4], bl[2][4];
#pragma unroll
            for (int p = 0; p < 2; p++) {
                ldsm4(bh[p], addrB_s(base + Q2_BH, wn + p * 16, ki * 16, lane, STR2));
                ldsm4(bl[p], addrB_s(base + Q2_BL, wn + p * 16, ki * 16, lane, STR2));
            }
#pragma unroll
            for (int mi = 0; mi < 4; mi++) {
                uint32_t ah[4], al[4];
                ldsm4(ah, addrA_s(base + Q2_AH, wm + mi * 16, ki * 16, lane, STR2));
                ldsm4(al, addrA_s(base + Q2_AL, wm + mi * 16, ki * 16, lane, STR2));
#pragma unroll
                for (int nj = 0; nj < 4; nj++) {
                    const uint32_t* bhp = &bh[nj >> 1][(nj & 1) * 2];
                    const uint32_t* blp = &bl[nj >> 1][(nj & 1) * 2];
                    mma16816h(acc[mi][nj], ah, bhp, acc[mi][nj]);
                    mma16816h(acc[mi][nj], al, bhp, acc[mi][nj]);
                    mma16816h(acc[mi][nj], ah, blp, acc[mi][nj]);
                }
            }
        }
    }

    if (which == 0) {
#pragma unroll
        for (int mi = 0; mi < 4; mi++) {
#pragma unroll
            for (int nj = 0; nj < 4; nj++) {
                int row = m0 + wm + mi * 16 + (lane >> 2);
                int col = n0 + wn + nj * 8 + 2 * (lane & 3);
                __half h0, l0, h1, l1;
                splith(acc[mi][nj][0], h0, l0); splith(acc[mi][nj][1], h1, l1);
                *(uint32_t*)&g_Qh[(size_t)row * NP + col] = pack2h(h0, h1);
                *(uint32_t*)&g_Ql[(size_t)row * NP + col] = pack2h(l0, l1);
                splith(acc[mi][nj][2], h0, l0); splith(acc[mi][nj][3], h1, l1);
                *(uint32_t*)&g_Qh[(size_t)(row + 8) * NP + col] = pack2h(h0, h1);
                *(uint32_t*)&g_Ql[(size_t)(row + 8) * NP + col] = pack2h(l0, l1);
            }
        }
    } else {
        // K: scale by log2(e) so softmax can use raw ex2
#pragma unroll
        for (int mi = 0; mi < 4; mi++) {
#pragma unroll
            for (int nj = 0; nj < 4; nj++) {
                int row = m0 + wm + mi * 16 + (lane >> 2);
                int col = n0 + wn + nj * 8 + 2 * (lane & 3);
                *(uint32_t*)&g_Kf[(size_t)row * NP + col] =
                    packh2(acc[mi][nj][0] * LOG2E, acc[mi][nj][1] * LOG2E);
                *(uint32_t*)&g_Kf[(size_t)(row + 8) * NP + col] =
                    packh2(acc[mi][nj][2] * LOG2E, acc[mi][nj][3] * LOG2E);
            }
        }
    }
}

__device__ __forceinline__ void v_path(char* sm, uint32_t sb,
                                       int m0, int n0, int tid, int wid, int lane,
                                       int wm, int wn) {
    float acc[4][4][4];
#pragma unroll
    for (int mi = 0; mi < 4; mi++)
#pragma unroll
        for (int nj = 0; nj < 4; nj++)
#pragma unroll
            for (int e = 0; e < 4; e++) acc[mi][nj][e] = 0.f;

    auto load_chunk = [&](int c, int stage) {
        uint32_t base = sb + stage * VST;
        const int k0 = c * 64;
#pragma unroll
        for (int i = 0; i < 4; i++) {
            int idx = i * 256 + tid;
            int row = idx >> 3, v = idx & 7;
            uint32_t so = (uint32_t)(row * STR + v * 8) * 2;
            CP_A16(base + V_A + so, g_Ahi + (size_t)(m0 + row) * INF + k0 + v * 8);
            CP_A16(base + V_B + so, g_Wvf + (size_t)(n0 + row) * INF + k0 + v * 8);
        }
        CP_COMMIT();
    };

    load_chunk(0, 0);

    for (int c = 0; c < 16; ++c) {
        const int s = c & 1;
        CP_WAIT0();
        __syncthreads();
        if (c < 15) load_chunk(c + 1, s ^ 1);

        uint32_t base = sb + s * VST;
#pragma unroll
        for (int ki = 0; ki < 4; ki++) {
            uint32_t bq[2][4];
#pragma unroll
            for (int p = 0; p < 2; p++)
                ldsm4(bq[p], addrB_s(base + V_B, wn + p * 16, ki * 16, lane, STR));
#pragma unroll
            for (int mi = 0; mi < 4; mi++) {
                uint32_t aq[4];
                ldsm4(aq, addrA_s(base + V_A, wm + mi * 16, ki * 16, lane, STR));
#pragma unroll
                for (int nj = 0; nj < 4; nj++)
                    mma16816h(acc[mi][nj], aq, &bq[nj >> 1][(nj & 1) * 2], acc[mi][nj]);
            }
        }
    }

#pragma unroll
    for (int mi = 0; mi < 4; mi++) {
#pragma unroll
        for (int nj = 0; nj < 4; nj++) {
            int row = m0 + wm + mi * 16 + (lane >> 2);
            int col = n0 + wn + nj * 8 + 2 * (lane & 3);
            *(uint32_t*)&g_Vf[(size_t)row * NP + col]       = packh2(acc[mi][nj][0], acc[mi][nj][1]);
            *(uint32_t*)&g_Vf[(size_t)(row + 8) * NP + col] = packh2(acc[mi][nj][2], acc[mi][nj][3]);
        }
    }
}

__global__ __launch_bounds__(256, 2) void qkv_mma() {
    extern __shared__ char sm[];
    uint32_t sb = smem_u32(sm);
    const int which = blockIdx.z;            // 0=Q, 1=K, 2=V
    const int m0 = blockIdx.y * 128;
    const int n0 = blockIdx.x * 128;
    const int tid = threadIdx.x, wid = tid >> 5, lane = tid & 31;
    const int wm = (wid >> 2) * 64;
    const int wn = (wid & 3) * 32;

    if (which < 2)
        qk_path(sm, sb, which, m0, n0, tid, wid, lane, wm, wn);
    else
        v_path(sm, sb, m0, n0, tid, wid, lane, wm, wn);
}

// ---------------------------------------------------------------------------
// Kernel 2: FA2 flash attention + FUSED output projection.
// 128 q-rows, 256 threads, KV chunks 64, 3-stage cp.async pipeline.
// Scores pre-scaled by log2e (via K); softmax uses raw ex2.approx.
// Rescale of ctx acc skipped (warp-uniform) when running max unchanged.
// ---------------------------------------------------------------------------
#define AQ_H 0
#define AQ_L 18432
#define A_KV0 36864
#define A_KF 0
#define A_VF 9216
#define AST  18432                  // stage stride (K fp16 + V fp16)
#define AT_SMEM (A_KV0 + 3*AST)     // 92160
#define WO_ST 9216                  // Wo chunk stage stride (64 rows x STR)

__global__ __launch_bounds__(256, 2) void attn_fa2(const float* __restrict__ bo,
                                                   float* __restrict__ out) {
    extern __shared__ char sm[];
    uint32_t sb = smem_u32(sm);
    const int bh = blockIdx.y;
    const int b = bh >> 3, h = bh & 7;
    const size_t hoff = ((size_t)b * SEQ + (size_t)h * 256) * NP;
    const __half* Qh = g_Qh + hoff;
    const __half* Ql = g_Ql + hoff;
    const __half* Kf = g_Kf + hoff;
    const __half* Vf = g_Vf + hoff;

    const int q0 = blockIdx.x * 128;
    const int tid = threadIdx.x, wid = tid >> 5, lane = tid & 31;

    auto load_kv = [&](int kt, int stage) {
        uint32_t base = sb + A_KV0 + stage * AST;
#pragma unroll
        for (int i = 0; i < 2; i++) {
            int id2 = i * 256 + tid;
            int row = id2 >> 3, v = id2 & 7;
            uint32_t so = (uint32_t)(row * STR + v * 8) * 2;
            size_t g = (size_t)(kt * 64 + row) * DPH + v * 8;
            CP_A16(base + A_KF + so, Kf + g);
            CP_A16(base + A_VF + so, Vf + g);
        }
        CP_COMMIT();
    };

    // Persistent Q region (fp16 hi + lo)
#pragma unroll
    for (int i = 0; i < 4; i++) {
        int idx = i * 256 + tid;
        int row = idx >> 3, v = idx & 7;
        uint32_t so = (uint32_t)(row * STR + v * 8) * 2;
        size_t g = (size_t)(q0 + row) * DPH + v * 8;
        *(uint4*)(sm + AQ_H + so) = *(const uint4*)(Qh + g);
        *(uint4*)(sm + AQ_L + so) = *(const uint4*)(Ql + g);
    }
    load_kv(0, 0);
    load_kv(1, 1);
    __syncthreads();

    uint32_t aqh[4][4];
#pragma unroll
    for (int ki = 0; ki < 4; ki++)
        ldsm4(aqh[ki], addrA_s(sb + AQ_H, wid * 16, ki * 16, lane, STR));

    float cacc[8][4];
#pragma unroll
    for (int nj = 0; nj < 8; nj++)
#pragma unroll
        for (int e = 0; e < 4; e++) cacc[nj][e] = 0.f;
    float m0 = -1e30f, m1 = -1e30f, l0 = 0.f, l1 = 0.f;

    int stage = 0;   // stage of chunk kt
    for (int kt = 0; kt < 32; kt++) {
        if (kt < 31) { CP_WAIT1(); } else { CP_WAIT0(); }
        __syncthreads();
        if (kt < 30) {
            int ns = stage + 2; if (ns >= 3) ns -= 3;
            load_kv(kt + 2, ns);
        }

        uint32_t base = sb + A_KV0 + stage * AST;

        // S' = Q @ K'^T  (scores pre-scaled by log2e via K')
        float sacc[8][4];
#pragma unroll
        for (int nj = 0; nj < 8; nj++)
#pragma unroll
            for (int e = 0; e < 4; e++) sacc[nj][e] = 0.f;
#pragma unroll
        for (int ki = 0; ki < 4; ki++) {
            uint32_t aql[4];
            ldsm4(aql, addrA_s(sb + AQ_L, wid * 16, ki * 16, lane, STR));
#pragma unroll
            for (int p = 0; p < 4; p++) {
                uint32_t kf2[4];
                ldsm4(kf2, addrB_s(base + A_KF, p * 16, ki * 16, lane, STR));
#pragma unroll
                for (int q = 0; q < 2; q++) {
                    int nj = 2 * p + q;
                    mma16816h(sacc[nj], aqh[ki], &kf2[q * 2], sacc[nj]);
                    mma16816h(sacc[nj], aql,     &kf2[q * 2], sacc[nj]);
                }
            }
        }

        // register softmax (base-2): rows r=lane>>2 (m0/l0) and r+8 (m1/l1)
        float mx0 = -1e30f, mx1 = -1e30f;
#pragma unroll
        for (int nj = 0; nj < 8; nj++) {
            mx0 = fmaxf(mx0, fmaxf(sacc[nj][0], sacc[nj][1]));
            mx1 = fmaxf(mx1, fmaxf(sacc[nj][2], sacc[nj][3]));
        }
        mx0 = fmaxf(mx0, __shfl_xor_sync(0xffffffffu, mx0, 1));
        mx0 = fmaxf(mx0, __shfl_xor_sync(0xffffffffu, mx0, 2));
        mx1 = fmaxf(mx1, __shfl_xor_sync(0xffffffffu, mx1, 1));
        mx1 = fmaxf(mx1, __shfl_xor_sync(0xffffffffu, mx1, 2));
        float mn0 = fmaxf(m0, mx0), mn1 = fmaxf(m1, mx1);
        float c0 = ex2f(m0 - mn0), c1 = ex2f(m1 - mn1);
        m0 = mn0; m1 = mn1;

        uint32_t aP[4][4];
        float ls0 = 0.f, ls1 = 0.f;
#pragma unroll
        for (int ki = 0; ki < 4; ki++) {
#pragma unroll
            for (int jj = 0; jj < 2; jj++) {
                int nj = 2 * ki + jj;
                float p0 = ex2f(sacc[nj][0] - mn0);
                float p1 = ex2f(sacc[nj][1] - mn0);
                float p2 = ex2f(sacc[nj][2] - mn1);
                float p3 = ex2f(sacc[nj][3] - mn1);
                ls0 += p0 + p1; ls1 += p2 + p3;
                aP[ki][2 * jj + 0] = packh2(p0, p1);
                aP[ki][2 * jj + 1] = packh2(p2, p3);
            }
        }
        ls0 += __shfl_xor_sync(0xffffffffu, ls0, 1);
        ls0 += __shfl_xor_sync(0xffffffffu, ls0, 2);
        ls1 += __shfl_xor_sync(0xffffffffu, ls1, 1);
        ls1 += __shfl_xor_sync(0xffffffffu, ls1, 2);
        l0 = l0 * c0 + ls0;
        l1 = l1 * c1 + ls1;

        // rescale ctx acc only if any lane's max changed (c != 1.0 exactly)
        if (!__all_sync(0xffffffffu, (c0 == 1.0f) && (c1 == 1.0f))) {
#pragma unroll
            for (int nj = 0; nj < 8; nj++) {
                cacc[nj][0] *= c0; cacc[nj][1] *= c0;
                cacc[nj][2] *= c1; cacc[nj][3] *= c1;
            }
        }

        // PV: single fp16 MMA per tile (fp32 acc)
#pragma unroll
        for (int ki = 0; ki < 4; ki++) {
#pragma unroll
            for (int p = 0; p < 4; p++) {
                uint32_t v2[4];
                ldsm4t(v2, addrV_s(base + A_VF, ki * 16, p * 16, lane, STR));
#pragma unroll
                for (int q = 0; q < 2; q++) {
                    int nj = 2 * p + q;
                    mma16816h(cacc[nj], aP[ki], &v2[q * 2], cacc[nj]);
                }
            }
        }

        if (++stage == 3) stage = 0;
    }

    // ---- fused output projection ----
    float inv0 = 1.0f / (8.0f * l0);   // post-softmax /sqrt(d) quirk
    float inv1 = 1.0f / (8.0f * l1);

    // ctx -> fp16 A-fragments
    uint32_t aC[4][4];
#pragma unroll
    for (int ki = 0; ki < 4; ki++) {
#pragma unroll
        for (int jj = 0; jj < 2; jj++) {
            int nj = 2 * ki + jj;
            aC[ki][2 * jj + 0] = packh2(cacc[nj][0] * inv0, cacc[nj][1] * inv0);
            aC[ki][2 * jj + 1] = packh2(cacc[nj][2] * inv1, cacc[nj][3] * inv1);
        }
    }
    __syncthreads();   // all warps done reading KV smem stages

    // Wo pipeline: 4 stages x 9216 B in the dead KV region, 3 loads in flight.
    const uint32_t WOB = sb + A_KV0;
    auto load_wo = [&](int ch, int st) {
#pragma unroll
        for (int i = 0; i < 2; i++) {
            int idx = i * 256 + tid;
            int wrow = idx >> 3, wv = idx & 7;
            uint32_t so = (uint32_t)(wrow * STR + wv * 8) * 2;
            CP_A16(WOB + st * WO_ST + so,
                   g_Wof + (size_t)(ch * 64 + wrow) * DPH + wv * 8);
        }
        CP_COMMIT();
    };
    load_wo(0, 0);
    load_wo(1, 1);
    load_wo(2, 2);

    const size_t grow = (size_t)bh * SEQ + q0 + wid * 16 + (lane >> 2);
    for (int ch = 0; ch < 16; ch++) {
        const int st = ch & 3;
        CP_WAIT2();
        __syncthreads();
        if (ch < 13) load_wo(ch + 3, (ch + 3) & 3);

        uint32_t base = WOB + st * WO_ST;
        float oacc[8][4];
#pragma unroll
        for (int nj = 0; nj < 8; nj++)
#pragma unroll
            for (int e = 0; e < 4; e++) oacc[nj][e] = 0.f;

#pragma unroll
        for (int ki = 0; ki < 4; ki++) {
#pragma unroll
            for (int p = 0; p < 4; p++) {
                uint32_t bq[4];
                ldsm4(bq, addrB_s(base, p * 16, ki * 16, lane, STR));
#pragma unroll
                for (int q = 0; q < 2; q++) {
                    int nj = 2 * p + q;
                    mma16816h(oacc[nj], aC[ki], &bq[q * 2], oacc[nj]);
                }
            }
        }

        const int nc0 = ch * 64;
#pragma unroll
        for (int nj = 0; nj < 8; nj++) {
            int col = nc0 + nj * 8 + 2 * (lane & 3);
            float2 bv = *(const float2*)&bo[col];
            *(float2*)&out[grow * OUTF + col] =
                make_float2(oacc[nj][0] + bv.x, oacc[nj][1] + bv.y);
            *(float2*)&out[(grow + 8) * OUTF + col] =
                make_float2(oacc[nj][2] + bv.x, oacc[nj][3] + bv.y);
        }
    }
}

// ---------------------------------------------------------------------------
extern "C" void kernel_launch(void* const* d_in, const int* in_sizes, int n_in,
                              void* d_out, int out_size)
{
    const float* inputs = (const float*)d_in[0];
    const float* Wq     = (const float*)d_in[1];
    const float* Wk     = (const float*)d_in[2];
    const float* Wv     = (const float*)d_in[3];
    const float* Wo     = (const float*)d_in[4];
    const float* bo     = (const float*)d_in[5];
    float* out = (float*)d_out;

    cudaFuncSetAttribute(qkv_mma, cudaFuncAttributeMaxDynamicSharedMemorySize, QG_SMEM);
    cudaFuncSetAttribute(attn_fa2, cudaFuncAttributeMaxDynamicSharedMemorySize, AT_SMEM);

    prep_all<<<PREP_A_BLKS + PREP_WT_BLKS + PREP_WO_BLKS, 256>>>(inputs, Wq, Wk, Wv, Wo);
    {
        dim3 grid(NP / 128, MROWS / 128, 3);   // z: Q, K, V — one launch, two code paths
        qkv_mma<<<grid, 256, QG_SMEM>>>();
    }
    {
        dim3 grid(SEQ / 128, BATCH * HEADS);
        attn_fa2<<<grid, 256, AT_SMEM>>>(bo, out);
    }
}

// round 16
// speedup vs baseline: 1.0022x; 1.0003x over previous
#include <cuda_runtime.h>
#include <cuda_bf16.h>
#include <cuda_fp16.h>
#include <cstdint>

// ---------------------------------------------------------------------------
// Problem constants
// ---------------------------------------------------------------------------
#define BATCH 2
#define SEQ   2048
#define INF   1024
#define HEADS 8
#define DPH   64
#define OUTF  1024
#define NP    512                 // HEADS*DPH
#define MROWS (BATCH*SEQ)         // 4096
#define PSZ   (MROWS*NP)          // elems per projection
#define CTXROWS (BATCH*HEADS*SEQ) // 32768
#define LOG2E 1.4426950408889634f

// Scratch (module-static device memory; no runtime allocation)
__device__ __half g_Ahi[MROWS * INF];      // inputs fp16 hi (also V-proj A)
__device__ __half g_Alo[MROWS * INF];      // inputs fp16 lo
__device__ __half g_Wthi[2 * NP * INF];    // Wq,Wk ^T fp16 hi [n][k]
__device__ __half g_Wtlo[2 * NP * INF];    // Wq,Wk ^T fp16 lo
__device__ __half g_Wvf[NP * INF];         // Wv^T fp16 single
__device__ __half g_Wof[OUTF * DPH];       // Wo^T fp16 single
__device__ __half g_Qh[PSZ];               // Q fp16 hi
__device__ __half g_Ql[PSZ];               // Q fp16 lo
__device__ __half g_Kf[PSZ];               // K * log2e, fp16 single
__device__ __half g_Vf[PSZ];               // V fp16 single

// ---------------------------------------------------------------------------
// Helpers
// ---------------------------------------------------------------------------
__device__ __forceinline__ uint32_t smem_u32(const void* p) {
    uint32_t a;
    asm("{ .reg .u64 t; cvta.to.shared.u64 t, %1; cvt.u32.u64 %0, t; }"
        : "=r"(a) : "l"(p));
    return a;
}

// fp16 inputs, fp32 accumulate
__device__ __forceinline__ void mma16816h(float d[4], const uint32_t a[4],
                                          const uint32_t b[2], const float c[4]) {
    asm volatile(
        "mma.sync.aligned.m16n8k16.row.col.f32.f16.f16.f32 "
        "{%0,%1,%2,%3}, {%4,%5,%6,%7}, {%8,%9}, {%10,%11,%12,%13};"
        : "=f"(d[0]), "=f"(d[1]), "=f"(d[2]), "=f"(d[3])
        : "r"(a[0]), "r"(a[1]), "r"(a[2]), "r"(a[3]),
          "r"(b[0]), "r"(b[1]),
          "f"(c[0]), "f"(c[1]), "f"(c[2]), "f"(c[3]));
}

__device__ __forceinline__ void ldsm4(uint32_t r[4], uint32_t addr) {
    asm volatile("ldmatrix.sync.aligned.m8n8.x4.shared.b16 {%0,%1,%2,%3}, [%4];"
                 : "=r"(r[0]), "=r"(r[1]), "=r"(r[2]), "=r"(r[3]) : "r"(addr));
}
__device__ __forceinline__ void ldsm4t(uint32_t r[4], uint32_t addr) {
    asm volatile("ldmatrix.sync.aligned.m8n8.x4.trans.shared.b16 {%0,%1,%2,%3}, [%4];"
                 : "=r"(r[0]), "=r"(r[1]), "=r"(r[2]), "=r"(r[3]) : "r"(addr));
}

#define CP_A16(dst, src) \
    asm volatile("cp.async.cg.shared.global [%0], [%1], 16;" :: "r"(dst), "l"(src) : "memory")
#define CP_COMMIT() asm volatile("cp.async.commit_group;" ::: "memory")
#define CP_WAIT0()  asm volatile("cp.async.wait_group 0;" ::: "memory")
#define CP_WAIT1()  asm volatile("cp.async.wait_group 1;" ::: "memory")
#define CP_WAIT2()  asm volatile("cp.async.wait_group 2;" ::: "memory")

__device__ __forceinline__ float ex2f(float x) {
    float r;
    asm("ex2.approx.f32 %0, %1;" : "=f"(r) : "f"(x));
    return r;
}

__device__ __forceinline__ void splith(float v, __half& h, __half& l) {
    h = __float2half_rn(v);
    l = __float2half_rn(v - __half2float(h));
}
__device__ __forceinline__ uint32_t pack2h(__half a, __half b) {
    __half2 p = __halves2half2(a, b);
    return *reinterpret_cast<uint32_t*>(&p);
}
__device__ __forceinline__ uint32_t packh2(float a, float b) {
    __half2 p = __floats2half2_rn(a, b);
    return *reinterpret_cast<uint32_t*>(&p);
}

// strides (elements) for mma operand tiles in smem
#define STR  72   // 144 B rows (64-col tiles)
#define STR2 40   // 80 B rows (32-col tiles)

__device__ __forceinline__ uint32_t addrA_s(uint32_t base, int brow, int bcol, int lane, int str) {
    int row = brow + (lane & 7) + ((lane & 8) ? 8 : 0);
    int col = bcol + ((lane & 16) ? 8 : 0);
    return base + (row * str + col) * 2;
}
__device__ __forceinline__ uint32_t addrB_s(uint32_t base, int brow, int bcol, int lane, int str) {
    int row = brow + (lane & 7) + ((lane & 16) ? 8 : 0);
    int col = bcol + ((lane & 8) ? 8 : 0);
    return base + (row * str + col) * 2;
}
__device__ __forceinline__ uint32_t addrV_s(uint32_t base, int kvrow, int dcol, int lane, int str) {
    int row = kvrow + (lane & 7) + ((lane & 8) ? 8 : 0);
    int col = dcol + ((lane & 16) ? 8 : 0);
    return base + (row * str + col) * 2;
}

// ---------------------------------------------------------------------------
// Fused prep kernel: one launch, block-range dispatch into three paths.
//   A path: 8 float4 per thread, loads front-batched (MLP=8) -> 512 blocks
// ---------------------------------------------------------------------------
#define PREP_A_BLKS  (MROWS * INF / 4 / 256 / 8)  // 512
#define PREP_WT_BLKS (3 * (INF/32) * (NP/32))     // 1536
#define PREP_WO_BLKS ((DPH/32) * (OUTF/32))       // 64

__global__ __launch_bounds__(256) void prep_all(const float* __restrict__ X,
                                                const float* __restrict__ Wq,
                                                const float* __restrict__ Wk,
                                                const float* __restrict__ Wv,
                                                const float* __restrict__ Wo) {
    __shared__ float t[32][33];
    const int blk = blockIdx.x;
    const int tid = threadIdx.x;

    if (blk < PREP_A_BLKS) {
        // front-batch 8 independent float4 loads (MLP=8), then convert+store
        float4 v[8];
#pragma unroll
        for (int j = 0; j < 8; j++)
            v[j] = ((const float4*)X)[blk * 2048 + j * 256 + tid];
#pragma unroll
        for (int j = 0; j < 8; j++) {
            int idx = blk * 2048 + j * 256 + tid;
            __half h0, h1, h2, h3, l0, l1, l2, l3;
            splith(v[j].x, h0, l0); splith(v[j].y, h1, l1);
            splith(v[j].z, h2, l2); splith(v[j].w, h3, l3);
            uint2 hh; hh.x = pack2h(h0, h1); hh.y = pack2h(h2, h3);
            uint2 ll; ll.x = pack2h(l0, l1); ll.y = pack2h(l2, l3);
            ((uint2*)g_Ahi)[idx] = hh;
            ((uint2*)g_Alo)[idx] = ll;
        }
    } else if (blk < PREP_A_BLKS + PREP_WT_BLKS) {
        int i = blk - PREP_A_BLKS;
        const int which = i / 512;
        int j = i % 512;
        const int k0 = (j % 32) * 32, n0 = (j / 32) * 32;
        const float* W = (which == 0) ? Wq : (which == 1) ? Wk : Wv;
        const int tx = tid & 31, ty = tid >> 5;
#pragma unroll
        for (int jj = 0; jj < 4; jj++)
            t[ty + jj * 8][tx] = W[(size_t)(k0 + ty + jj * 8) * NP + n0 + tx];
        __syncthreads();
#pragma unroll
        for (int jj = 0; jj < 4; jj++) {
            int n = n0 + ty + jj * 8, k = k0 + tx;
            float v = t[tx][ty + jj * 8];
            if (which < 2) {
                __half h, l; splith(v, h, l);
                size_t o = ((size_t)which * NP + n) * INF + k;
                g_Wthi[o] = h; g_Wtlo[o] = l;
            } else {
                g_Wvf[(size_t)n * INF + k] = __float2half_rn(v);
            }
        }
    } else {
        int i = blk - PREP_A_BLKS - PREP_WT_BLKS;
        const int k0 = (i % 2) * 32, n0 = (i / 2) * 32;
        const int tx = tid & 31, ty = tid >> 5;
#pragma unroll
        for (int jj = 0; jj < 4; jj++)
            t[ty + jj * 8][tx] = Wo[(size_t)(k0 + ty + jj * 8) * OUTF + n0 + tx];
        __syncthreads();
#pragma unroll
        for (int jj = 0; jj < 4; jj++) {
            int n = n0 + ty + jj * 8, k = k0 + tx;
            g_Wof[(size_t)n * DPH + k] = __float2half_rn(t[tx][ty + jj * 8]);
        }
    }
}

// ---------------------------------------------------------------------------
// Kernel 1: fused QKV. Top-level dispatch on blockIdx.z into two SEPARATE
// fully-pipelined paths. K is stored pre-scaled by log2(e).
// ---------------------------------------------------------------------------
#define Q2_MAT (128*STR2*2)        // 10240 per matrix
#define Q2_AH 0
#define Q2_AL Q2_MAT
#define Q2_BH (2*Q2_MAT)
#define Q2_BL (3*Q2_MAT)
#define Q2ST  (4*Q2_MAT)           // 40960 stage stride
#define QG_SMEM (2*Q2ST)           // 81920

#define V_A 0
#define V_B 18432
#define VST 36864                  // V stage stride

__device__ __forceinline__ void qk_path(char* sm, uint32_t sb, int which,
                                        int m0, int n0, int tid, int wid, int lane,
                                        int wm, int wn) {
    const __half* Bh = g_Wthi + (size_t)which * NP * INF;
    const __half* Bl = g_Wtlo + (size_t)which * NP * INF;

    float acc[4][4][4];
#pragma unroll
    for (int mi = 0; mi < 4; mi++)
#pragma unroll
        for (int nj = 0; nj < 4; nj++)
#pragma unroll
            for (int e = 0; e < 4; e++) acc[mi][nj][e] = 0.f;

    auto load_chunk = [&](int c, int stage) {
        uint32_t base = sb + stage * Q2ST;
        const int k0 = c * 32;
#pragma unroll
        for (int i = 0; i < 2; i++) {
            int idx = i * 256 + tid;
            int row = idx >> 2, v = idx & 3;
            uint32_t so = (uint32_t)(row * STR2 + v * 8) * 2;
            size_t gA = (size_t)(m0 + row) * INF + k0 + v * 8;
            size_t gB = (size_t)(n0 + row) * INF + k0 + v * 8;
            CP_A16(base + Q2_AH + so, g_Ahi + gA);
            CP_A16(base + Q2_AL + so, g_Alo + gA);
            CP_A16(base + Q2_BH + so, Bh + gB);
            CP_A16(base + Q2_BL + so, Bl + gB);
        }
        CP_COMMIT();
    };

    load_chunk(0, 0);

    for (int c = 0; c < 32; ++c) {
        const int s = c & 1;
        CP_WAIT0();
        __syncthreads();
        if (c < 31) load_chunk(c + 1, s ^ 1);

        uint32_t base = sb + s * Q2ST;
#pragma unroll
        for (int ki = 0; ki < 2; ki++) {
            uint32_t bh[2][4], bl[2][4];
#pragma unroll
            for (int p = 0; p < 2; p++) {
                ldsm4(bh[p], addrB_s(base + Q2_BH, wn + p * 16, ki * 16, lane, STR2));
                ldsm4(bl[p], addrB_s(base + Q2_BL, wn + p * 16, ki * 16, lane, STR2));
            }
#pragma unroll
            for (int mi = 0; mi < 4; mi++) {
                uint32_t ah[4], al[4];
                ldsm4(ah, addrA_s(base + Q2_AH, wm + mi * 16, ki * 16, lane, STR2));
                ldsm4(al, addrA_s(base + Q2_AL, wm + mi * 16, ki * 16, lane, STR2));
#pragma unroll
                for (int nj = 0; nj < 4; nj++) {
                    const uint32_t* bhp = &bh[nj >> 1][(nj & 1) * 2];
                    const uint32_t* blp = &bl[nj >> 1][(nj & 1) * 2];
                    mma16816h(acc[mi][nj], ah, bhp, acc[mi][nj]);
                    mma16816h(acc[mi][nj], al, bhp, acc[mi][nj]);
                    mma16816h(acc[mi][nj], ah, blp, acc[mi][nj]);
                }
            }
        }
    }

    if (which == 0) {
#pragma unroll
        for (int mi = 0; mi < 4; mi++) {
#pragma unroll
            for (int nj = 0; nj < 4; nj++) {
                int row = m0 + wm + mi * 16 + (lane >> 2);
                int col = n0 + wn + nj * 8 + 2 * (lane & 3);
                __half h0, l0, h1, l1;
                splith(acc[mi][nj][0], h0, l0); splith(acc[mi][nj][1], h1, l1);
                *(uint32_t*)&g_Qh[(size_t)row * NP + col] = pack2h(h0, h1);
                *(uint32_t*)&g_Ql[(size_t)row * NP + col] = pack2h(l0, l1);
                splith(acc[mi][nj][2], h0, l0); splith(acc[mi][nj][3], h1, l1);
                *(uint32_t*)&g_Qh[(size_t)(row + 8) * NP + col] = pack2h(h0, h1);
                *(uint32_t*)&g_Ql[(size_t)(row + 8) * NP + col] = pack2h(l0, l1);
            }
        }
    } else {
        // K: scale by log2(e) so softmax can use raw ex2
#pragma unroll
        for (int mi = 0; mi < 4; mi++) {
#pragma unroll
            for (int nj = 0; nj < 4; nj++) {
                int row = m0 + wm + mi * 16 + (lane >> 2);
                int col = n0 + wn + nj * 8 + 2 * (lane & 3);
                *(uint32_t*)&g_Kf[(size_t)row * NP + col] =
                    packh2(acc[mi][nj][0] * LOG2E, acc[mi][nj][1] * LOG2E);
                *(uint32_t*)&g_Kf[(size_t)(row + 8) * NP + col] =
                    packh2(acc[mi][nj][2] * LOG2E, acc[mi][nj][3] * LOG2E);
            }
        }
    }
}

__device__ __forceinline__ void v_path(char* sm, uint32_t sb,
                                       int m0, int n0, int tid, int wid, int lane,
                                       int wm, int wn) {
    float acc[4][4][4];
#pragma unroll
    for (int mi = 0; mi < 4; mi++)
#pragma unroll
        for (int nj = 0; nj < 4; nj++)
#pragma unroll
            for (int e = 0; e < 4; e++) acc[mi][nj][e] = 0.f;

    auto load_chunk = [&](int c, int stage) {
        uint32_t base = sb + stage * VST;
        const int k0 = c * 64;
#pragma unroll
        for (int i = 0; i < 4; i++) {
            int idx = i * 256 + tid;
            int row = idx >> 3, v = idx & 7;
            uint32_t so = (uint32_t)(row * STR + v * 8) * 2;
            CP_A16(base + V_A + so, g_Ahi + (size_t)(m0 + row) * INF + k0 + v * 8);
            CP_A16(base + V_B + so, g_Wvf + (size_t)(n0 + row) * INF + k0 + v * 8);
        }
        CP_COMMIT();
    };

    load_chunk(0, 0);

    for (int c = 0; c < 16; ++c) {
        const int s = c & 1;
        CP_WAIT0();
        __syncthreads();
        if (c < 15) load_chunk(c + 1, s ^ 1);

        uint32_t base = sb + s * VST;
#pragma unroll
        for (int ki = 0; ki < 4; ki++) {
            uint32_t bq[2][4];
#pragma unroll
            for (int p = 0; p < 2; p++)
                ldsm4(bq[p], addrB_s(base + V_B, wn + p * 16, ki * 16, lane, STR));
#pragma unroll
            for (int mi = 0; mi < 4; mi++) {
                uint32_t aq[4];
                ldsm4(aq, addrA_s(base + V_A, wm + mi * 16, ki * 16, lane, STR));
#pragma unroll
                for (int nj = 0; nj < 4; nj++)
                    mma16816h(acc[mi][nj], aq, &bq[nj >> 1][(nj & 1) * 2], acc[mi][nj]);
            }
        }
    }

#pragma unroll
    for (int mi = 0; mi < 4; mi++) {
#pragma unroll
        for (int nj = 0; nj < 4; nj++) {
            int row = m0 + wm + mi * 16 + (lane >> 2);
            int col = n0 + wn + nj * 8 + 2 * (lane & 3);
            *(uint32_t*)&g_Vf[(size_t)row * NP + col]       = packh2(acc[mi][nj][0], acc[mi][nj][1]);
            *(uint32_t*)&g_Vf[(size_t)(row + 8) * NP + col] = packh2(acc[mi][nj][2], acc[mi][nj][3]);
        }
    }
}

__global__ __launch_bounds__(256, 2) void qkv_mma() {
    extern __shared__ char sm[];
    uint32_t sb = smem_u32(sm);
    const int which = blockIdx.z;            // 0=Q, 1=K, 2=V
    const int m0 = blockIdx.y * 128;
    const int n0 = blockIdx.x * 128;
    const int tid = threadIdx.x, wid = tid >> 5, lane = tid & 31;
    const int wm = (wid >> 2) * 64;
    const int wn = (wid & 3) * 32;

    if (which < 2)
        qk_path(sm, sb, which, m0, n0, tid, wid, lane, wm, wn);
    else
        v_path(sm, sb, m0, n0, tid, wid, lane, wm, wn);
}

// ---------------------------------------------------------------------------
// Kernel 2: FA2 flash attention + FUSED output projection.
// 128 q-rows, 256 threads, KV chunks 64, 3-stage cp.async pipeline.
// Scores pre-scaled by log2e (via K); softmax uses raw ex2.approx.
// Rescale of ctx acc skipped (warp-uniform) when running max unchanged.
// ---------------------------------------------------------------------------
#define AQ_H 0
#define AQ_L 18432
#define A_KV0 36864
#define A_KF 0
#define A_VF 9216
#define AST  18432                  // stage stride (K fp16 + V fp16)
#define AT_SMEM (A_KV0 + 3*AST)     // 92160
#define WO_ST 9216                  // Wo chunk stage stride (64 rows x STR)

__global__ __launch_bounds__(256, 2) void attn_fa2(const float* __restrict__ bo,
                                                   float* __restrict__ out) {
    extern __shared__ char sm[];
    uint32_t sb = smem_u32(sm);
    const int bh = blockIdx.y;
    const int b = bh >> 3, h = bh & 7;
    const size_t hoff = ((size_t)b * SEQ + (size_t)h * 256) * NP;
    const __half* Qh = g_Qh + hoff;
    const __half* Ql = g_Ql + hoff;
    const __half* Kf = g_Kf + hoff;
    const __half* Vf = g_Vf + hoff;

    const int q0 = blockIdx.x * 128;
    const int tid = threadIdx.x, wid = tid >> 5, lane = tid & 31;

    auto load_kv = [&](int kt, int stage) {
        uint32_t base = sb + A_KV0 + stage * AST;
#pragma unroll
        for (int i = 0; i < 2; i++) {
            int id2 = i * 256 + tid;
            int row = id2 >> 3, v = id2 & 7;
            uint32_t so = (uint32_t)(row * STR + v * 8) * 2;
            size_t g = (size_t)(kt * 64 + row) * DPH + v * 8;
            CP_A16(base + A_KF + so, Kf + g);
            CP_A16(base + A_VF + so, Vf + g);
        }
        CP_COMMIT();
    };

    // Persistent Q region (fp16 hi + lo)
#pragma unroll
    for (int i = 0; i < 4; i++) {
        int idx = i * 256 + tid;
        int row = idx >> 3, v = idx & 7;
        uint32_t so = (uint32_t)(row * STR + v * 8) * 2;
        size_t g = (size_t)(q0 + row) * DPH + v * 8;
        *(uint4*)(sm + AQ_H + so) = *(const uint4*)(Qh + g);
        *(uint4*)(sm + AQ_L + so) = *(const uint4*)(Ql + g);
    }
    load_kv(0, 0);
    load_kv(1, 1);
    __syncthreads();

    uint32_t aqh[4][4];
#pragma unroll
    for (int ki = 0; ki < 4; ki++)
        ldsm4(aqh[ki], addrA_s(sb + AQ_H, wid * 16, ki * 16, lane, STR));

    float cacc[8][4];
#pragma unroll
    for (int nj = 0; nj < 8; nj++)
#pragma unroll
        for (int e = 0; e < 4; e++) cacc[nj][e] = 0.f;
    float m0 = -1e30f, m1 = -1e30f, l0 = 0.f, l1 = 0.f;

    int stage = 0;   // stage of chunk kt
    for (int kt = 0; kt < 32; kt++) {
        if (kt < 31) { CP_WAIT1(); } else { CP_WAIT0(); }
        __syncthreads();
        if (kt < 30) {
            int ns = stage + 2; if (ns >= 3) ns -= 3;
            load_kv(kt + 2, ns);
        }

        uint32_t base = sb + A_KV0 + stage * AST;

        // S' = Q @ K'^T  (scores pre-scaled by log2e via K')
        float sacc[8][4];
#pragma unroll
        for (int nj = 0; nj < 8; nj++)
#pragma unroll
            for (int e = 0; e < 4; e++) sacc[nj][e] = 0.f;
#pragma unroll
        for (int ki = 0; ki < 4; ki++) {
            uint32_t aql[4];
            ldsm4(aql, addrA_s(sb + AQ_L, wid * 16, ki * 16, lane, STR));
#pragma unroll
            for (int p = 0; p < 4; p++) {
                uint32_t kf2[4];
                ldsm4(kf2, addrB_s(base + A_KF, p * 16, ki * 16, lane, STR));
#pragma unroll
                for (int q = 0; q < 2; q++) {
                    int nj = 2 * p + q;
                    mma16816h(sacc[nj], aqh[ki], &kf2[q * 2], sacc[nj]);
                    mma16816h(sacc[nj], aql,     &kf2[q * 2], sacc[nj]);
                }
            }
        }

        // register softmax (base-2): rows r=lane>>2 (m0/l0) and r+8 (m1/l1)
        float mx0 = -1e30f, mx1 = -1e30f;
#pragma unroll
        for (int nj = 0; nj < 8; nj++) {
            mx0 = fmaxf(mx0, fmaxf(sacc[nj][0], sacc[nj][1]));
            mx1 = fmaxf(mx1, fmaxf(sacc[nj][2], sacc[nj][3]));
        }
        mx0 = fmaxf(mx0, __shfl_xor_sync(0xffffffffu, mx0, 1));
        mx0 = fmaxf(mx0, __shfl_xor_sync(0xffffffffu, mx0, 2));
        mx1 = fmaxf(mx1, __shfl_xor_sync(0xffffffffu, mx1, 1));
        mx1 = fmaxf(mx1, __shfl_xor_sync(0xffffffffu, mx1, 2));
        float mn0 = fmaxf(m0, mx0), mn1 = fmaxf(m1, mx1);
        float c0 = ex2f(m0 - mn0), c1 = ex2f(m1 - mn1);
        m0 = mn0; m1 = mn1;

        uint32_t aP[4][4];
        float ls0 = 0.f, ls1 = 0.f;
#pragma unroll
        for (int ki = 0; ki < 4; ki++) {
#pragma unroll
            for (int jj = 0; jj < 2; jj++) {
                int nj = 2 * ki + jj;
                float p0 = ex2f(sacc[nj][0] - mn0);
                float p1 = ex2f(sacc[nj][1] - mn0);
                float p2 = ex2f(sacc[nj][2] - mn1);
                float p3 = ex2f(sacc[nj][3] - mn1);
                ls0 += p0 + p1; ls1 += p2 + p3;
                aP[ki][2 * jj + 0] = packh2(p0, p1);
                aP[ki][2 * jj + 1] = packh2(p2, p3);
            }
        }
        ls0 += __shfl_xor_sync(0xffffffffu, ls0, 1);
        ls0 += __shfl_xor_sync(0xffffffffu, ls0, 2);
        ls1 += __shfl_xor_sync(0xffffffffu, ls1, 1);
        ls1 += __shfl_xor_sync(0xffffffffu, ls1, 2);
        l0 = l0 * c0 + ls0;
        l1 = l1 * c1 + ls1;

        // rescale ctx acc only if any lane's max changed (c != 1.0 exactly)
        if (!__all_sync(0xffffffffu, (c0 == 1.0f) && (c1 == 1.0f))) {
#pragma unroll
            for (int nj = 0; nj < 8; nj++) {
                cacc[nj][0] *= c0; cacc[nj][1] *= c0;
                cacc[nj][2] *= c1; cacc[nj][3] *= c1;
            }
        }

        // PV: single fp16 MMA per tile (fp32 acc)
#pragma unroll
        for (int ki = 0; ki < 4; ki++) {
#pragma unroll
            for (int p = 0; p < 4; p++) {
                uint32_t v2[4];
                ldsm4t(v2, addrV_s(base + A_VF, ki * 16, p * 16, lane, STR));
#pragma unroll
                for (int q = 0; q < 2; q++) {
                    int nj = 2 * p + q;
                    mma16816h(cacc[nj], aP[ki], &v2[q * 2], cacc[nj]);
                }
            }
        }

        if (++stage == 3) stage = 0;
    }

    // ---- fused output projection ----
    float inv0 = 1.0f / (8.0f * l0);   // post-softmax /sqrt(d) quirk
    float inv1 = 1.0f / (8.0f * l1);

    // ctx -> fp16 A-fragments
    uint32_t aC[4][4];
#pragma unroll
    for (int ki = 0; ki < 4; ki++) {
#pragma unroll
        for (int jj = 0; jj < 2; jj++) {
            int nj = 2 * ki + jj;
            aC[ki][2 * jj + 0] = packh2(cacc[nj][0] * inv0, cacc[nj][1] * inv0);
            aC[ki][2 * jj + 1] = packh2(cacc[nj][2] * inv1, cacc[nj][3] * inv1);
        }
    }
    __syncthreads();   // all warps done reading KV smem stages

    // Wo pipeline: 4 stages x 9216 B in the dead KV region, 3 loads in flight.
    const uint32_t WOB = sb + A_KV0;
    auto load_wo = [&](int ch, int st) {
#pragma unroll
        for (int i = 0; i < 2; i++) {
            int idx = i * 256 + tid;
            int wrow = idx >> 3, wv = idx & 7;
            uint32_t so = (uint32_t)(wrow * STR + wv * 8) * 2;
            CP_A16(WOB + st * WO_ST + so,
                   g_Wof + (size_t)(ch * 64 + wrow) * DPH + wv * 8);
        }
        CP_COMMIT();
    };
    load_wo(0, 0);
    load_wo(1, 1);
    load_wo(2, 2);

    const size_t grow = (size_t)bh * SEQ + q0 + wid * 16 + (lane >> 2);
    for (int ch = 0; ch < 16; ch++) {
        const int st = ch & 3;
        CP_WAIT2();
        __syncthreads();
        if (ch < 13) load_wo(ch + 3, (ch + 3) & 3);

        uint32_t base = WOB + st * WO_ST;
        float oacc[8][4];
#pragma unroll
        for (int nj = 0; nj < 8; nj++)
#pragma unroll
            for (int e = 0; e < 4; e++) oacc[nj][e] = 0.f;

#pragma unroll
        for (int ki = 0; ki < 4; ki++) {
#pragma unroll
            for (int p = 0; p < 4; p++) {
                uint32_t bq[4];
                ldsm4(bq, addrB_s(base, p * 16, ki * 16, lane, STR));
#pragma unroll
                for (int q = 0; q < 2; q++) {
                    int nj = 2 * p + q;
                    mma16816h(oacc[nj], aC[ki], &bq[q * 2], oacc[nj]);
                }
            }
        }

        const int nc0 = ch * 64;
#pragma unroll
        for (int nj = 0; nj < 8; nj++) {
            int col = nc0 + nj * 8 + 2 * (lane & 3);
            float2 bv = *(const float2*)&bo[col];
            *(float2*)&out[grow * OUTF + col] =
                make_float2(oacc[nj][0] + bv.x, oacc[nj][1] + bv.y);
            *(float2*)&out[(grow + 8) * OUTF + col] =
                make_float2(oacc[nj][2] + bv.x, oacc[nj][3] + bv.y);
        }
    }
}

// ---------------------------------------------------------------------------
extern "C" void kernel_launch(void* const* d_in, const int* in_sizes, int n_in,
                              void* d_out, int out_size)
{
    const float* inputs = (const float*)d_in[0];
    const float* Wq     = (const float*)d_in[1];
    const float* Wk     = (const float*)d_in[2];
    const float* Wv     = (const float*)d_in[3];
    const float* Wo     = (const float*)d_in[4];
    const float* bo     = (const float*)d_in[5];
    float* out = (float*)d_out;

    cudaFuncSetAttribute(qkv_mma, cudaFuncAttributeMaxDynamicSharedMemorySize, QG_SMEM);
    cudaFuncSetAttribute(attn_fa2, cudaFuncAttributeMaxDynamicSharedMemorySize, AT_SMEM);

    prep_all<<<PREP_A_BLKS + PREP_WT_BLKS + PREP_WO_BLKS, 256>>>(inputs, Wq, Wk, Wv, Wo);
    {
        dim3 grid(NP / 128, MROWS / 128, 3);   // z: Q, K, V — one launch, two code paths
        qkv_mma<<<grid, 256, QG_SMEM>>>();
    }
    {
        dim3 grid(SEQ / 128, BATCH * HEADS);
        attn_fa2<<<grid, 256, AT_SMEM>>>(bo, out);
    }
}